// round 15
// baseline (speedup 1.0000x reference)
#include <cuda_runtime.h>
#include <cuda_fp16.h>
#include <math.h>
#include <cstdint>

// ---------------------------------------------------------------------------
// Problem constants: B=8, C=512, H=W=96, heads=8, dh=64
// seq layout: [768, 96, 512]  (n = b*96 + w, t = h, channel c)
// ---------------------------------------------------------------------------
#define TOTE 37748736  // 768*96*512

__device__ __half g_hb[5][TOTE];     // fp16 activation buffers
__device__ __half g_dwh[TOTE];       // dwconv output (separate so it can overlap)
__device__ __half g_wh[7 * 262144];  // fp16 weights: Wk,Wv,cWv,Wo,cWq,cWo,pw
__device__ float  g_bnscale[512];
__device__ float  g_bnbias[512];

__device__ __forceinline__ float fast_exp(float x) {
    x = fmaxf(x, -87.0f);
    float t = x * 1.44269504088896f;
    float fi = floorf(t);
    float f = t - fi;
    float p = 1.54035304e-4f;
    p = fmaf(p, f, 1.33335581e-3f);
    p = fmaf(p, f, 9.61812910e-3f);
    p = fmaf(p, f, 5.55041087e-2f);
    p = fmaf(p, f, 2.40226507e-1f);
    p = fmaf(p, f, 6.93147181e-1f);
    p = fmaf(p, f, 1.0f);
    return p * __int_as_float(((int)fi + 127) << 23);
}

#define MMA_F16(c0,c1,c2,c3,a0,a1,a2,a3,b0,b1) \
    asm volatile("mma.sync.aligned.m16n8k16.row.col.f32.f16.f16.f32 " \
                 "{%0,%1,%2,%3},{%4,%5,%6,%7},{%8,%9},{%0,%1,%2,%3};" \
                 : "+f"(c0),"+f"(c1),"+f"(c2),"+f"(c3) \
                 : "r"(a0),"r"(a1),"r"(a2),"r"(a3),"r"(b0),"r"(b1))

#define LDSM_X4(r0,r1,r2,r3,addr) \
    asm volatile("ldmatrix.sync.aligned.m8n8.x4.shared.b16 {%0,%1,%2,%3}, [%4];" \
                 : "=r"(r0),"=r"(r1),"=r"(r2),"=r"(r3) : "r"(addr))

#define LDSM_X4T(r0,r1,r2,r3,addr) \
    asm volatile("ldmatrix.sync.aligned.m8n8.x4.trans.shared.b16 {%0,%1,%2,%3}, [%4];" \
                 : "=r"(r0),"=r"(r1),"=r"(r2),"=r"(r3) : "r"(addr))

#define CP16(dst, src) \
    asm volatile("cp.async.cg.shared.global [%0], [%1], 16;" :: "r"(dst), "l"(src))
#define CP_COMMIT() asm volatile("cp.async.commit_group;")
#define CP_WAIT0()  asm volatile("cp.async.wait_group 0;")
#define CP_WAIT2()  asm volatile("cp.async.wait_group 2;")

__device__ __forceinline__ unsigned h2pack(float a, float b) {
    unsigned r;
    asm("cvt.rn.f16x2.f32 %0, %2, %1;" : "=r"(r) : "f"(a), "f"(b));
    return r;
}

// ---------------------------------------------------------------------------
// Weight prep: fp16-round 7 [512x512] matrices into g_wh (slot order = arg order)
// ---------------------------------------------------------------------------
__global__ void wprep(const float* __restrict__ a0, const float* __restrict__ a1,
                      const float* __restrict__ a2, const float* __restrict__ a3,
                      const float* __restrict__ a4, const float* __restrict__ a5,
                      const float* __restrict__ a6) {
    int i = blockIdx.x * 256 + threadIdx.x;
    int mat = i >> 16;
    int off = (i & 65535) * 4;
    const float* s;
    switch (mat) {
        case 0: s = a0; break; case 1: s = a1; break; case 2: s = a2; break;
        case 3: s = a3; break; case 4: s = a4; break; case 5: s = a5; break;
        default: s = a6; break;
    }
    float4 v = *(const float4*)(s + off);
    *(__half2*)(g_wh + (size_t)mat * 262144 + off)     = __floats2half2_rn(v.x, v.y);
    *(__half2*)(g_wh + (size_t)mat * 262144 + off + 2) = __floats2half2_rn(v.z, v.w);
}

// ---------------------------------------------------------------------------
// Layout transposes (c <-> w per (b,h) plane) — 64c x 32w tiles, 512 threads,
// 128B segments on both global sides.
// ---------------------------------------------------------------------------
// img fp32 [b,c,h,w] -> seq half [(b*96+w)*96+h, c]
__global__ __launch_bounds__(512) void img2seq(const float* __restrict__ img,
                                               __half* __restrict__ seq) {
    __shared__ float tile[64][33];
    int bh = blockIdx.z;
    int b = bh / 96, h = bh % 96;
    int c0 = blockIdx.y * 64, w0 = blockIdx.x * 32;
    int tx = threadIdx.x, ty = threadIdx.y;          // (32,16)
#pragma unroll
    for (int i = 0; i < 4; i++) {
        int crow = ty + i * 16;
        tile[crow][tx] = img[(((size_t)b * 512 + c0 + crow) * 96 + h) * 96 + w0 + tx];
    }
    __syncthreads();
    int sid = ty * 32 + tx;
    int cc = sid & 63, wq = sid >> 6;                // cc 0..63, wq 0..7
#pragma unroll
    for (int i = 0; i < 4; i++) {
        int w = wq + i * 8;
        seq[(((size_t)(b * 96 + w0 + w)) * 96 + h) * 512 + c0 + cc] =
            __float2half_rn(tile[cc][w]);
    }
}

// seq half -> img half (c <-> w)
__global__ __launch_bounds__(512) void seq2img_hh(const __half* __restrict__ seq,
                                                  __half* __restrict__ img) {
    __shared__ __half tile[64][33];
    int bh = blockIdx.z;
    int b = bh / 96, h = bh % 96;
    int c0 = blockIdx.y * 64, w0 = blockIdx.x * 32;
    int tx = threadIdx.x, ty = threadIdx.y;          // (64,8)
#pragma unroll
    for (int i = 0; i < 4; i++) {
        int w = ty + i * 8;
        tile[tx][w] = seq[(((size_t)(b * 96 + w0 + w)) * 96 + h) * 512 + c0 + tx];
    }
    __syncthreads();
    int sid = ty * 64 + tx;
    int ww = sid & 31, cq = sid >> 5;                // ww 0..31, cq 0..15
#pragma unroll
    for (int i = 0; i < 4; i++) {
        int c = cq + i * 16;
        img[(((size_t)b * 512 + c0 + c) * 96 + h) * 96 + w0 + ww] = tile[c][ww];
    }
}

// ---------------------------------------------------------------------------
// fp16 GEMM, multi-output: 128x128 tile, k-chunk 32, 4-stage cp.async,
// 256 threads (validated config; part of the measured-1390 build).
// ---------------------------------------------------------------------------
__global__ __launch_bounds__(256, 2) void gemm_h(
    const __half* __restrict__ A, const __half* __restrict__ Wb,
    const __half* __restrict__ Add, const float* __restrict__ bias,
    __half* __restrict__ o0, __half* __restrict__ o1, __half* __restrict__ o2,
    int mode0, int mode1, int mode2)
{
    extern __shared__ char smc[];
    unsigned sa = (unsigned)__cvta_generic_to_shared(smc);
    unsigned sw = sa + 40960;          // 4 stages x 5120 halves x 2B
    int m0 = blockIdx.y * 128;
    int nmat = blockIdx.x >> 2;
    int ncol0 = (blockIdx.x & 3) * 128;
    const __half* Wp = Wb + (size_t)blockIdx.x * 128 * 512;
    __half* Cout; int mode;
    if (nmat == 0)      { Cout = o0; mode = mode0; }
    else if (nmat == 1) { Cout = o1; mode = mode1; }
    else                { Cout = o2; mode = mode2; }

    int tid = threadIdx.x;
    int w = tid >> 5, l = tid & 31;
    int g = l >> 2, t = l & 3;
    int wm = (w & 1) * 64, wn = (w >> 1) * 32;
    int u = tid & 3, r0 = tid >> 2;    // 16B chunk, row 0..63

    int p = l & 7, sel = l >> 3;
    unsigned a_off = (unsigned)(((wm + p + (sel & 1) * 8) * 40 + (sel >> 1) * 8) * 2);
    unsigned b_off = (unsigned)(((p + (sel & 1) * 8) * 40 + (sel >> 1) * 8) * 2);

    float c[4][4][4];
#pragma unroll
    for (int mi = 0; mi < 4; mi++)
#pragma unroll
        for (int ni = 0; ni < 4; ni++)
#pragma unroll
            for (int r = 0; r < 4; r++) c[mi][ni][r] = 0.f;

#define GH_LOAD(st, kc) do { \
    const __half* Ag = A  + (size_t)(m0 + r0) * 512 + (kc) * 32 + u * 8; \
    const __half* Wg = Wp + (size_t)r0 * 512 + (kc) * 32 + u * 8; \
    unsigned da = sa + (unsigned)((st) * 10240 + (r0 * 40 + u * 8) * 2); \
    unsigned dw = sw + (unsigned)((st) * 10240 + (r0 * 40 + u * 8) * 2); \
    CP16(da, Ag); CP16(da + 5120, Ag + (size_t)64 * 512); \
    CP16(dw, Wg); CP16(dw + 5120, Wg + (size_t)64 * 512); \
    CP_COMMIT(); } while (0)

    GH_LOAD(0, 0); GH_LOAD(1, 1); GH_LOAD(2, 2);
#pragma unroll 1
    for (int kt = 0; kt < 16; kt++) {
        int cur = kt & 3;
        CP_WAIT2();
        __syncthreads();
        if (kt < 13) { GH_LOAD((kt + 3) & 3, kt + 3); } else { CP_COMMIT(); }
        unsigned cb = (unsigned)(cur * 10240);
#pragma unroll
        for (int ks = 0; ks < 2; ks++) {
            unsigned kofs = (unsigned)(ks * 32);
            unsigned a[4][4];
#pragma unroll
            for (int mi = 0; mi < 4; mi++) {
                unsigned addr = sa + cb + a_off + (unsigned)(mi * 16 * 80) + kofs;
                LDSM_X4(a[mi][0], a[mi][1], a[mi][2], a[mi][3], addr);
            }
            unsigned b[4][2];
#pragma unroll
            for (int nj = 0; nj < 2; nj++) {
                unsigned addr = sw + cb + b_off + (unsigned)((wn + nj * 16) * 80) + kofs;
                unsigned q0, q1, q2, q3;
                LDSM_X4(q0, q1, q2, q3, addr);
                b[nj * 2][0] = q0;     b[nj * 2][1] = q2;
                b[nj * 2 + 1][0] = q1; b[nj * 2 + 1][1] = q3;
            }
#pragma unroll
            for (int mi = 0; mi < 4; mi++)
#pragma unroll
                for (int ni = 0; ni < 4; ni++)
                    MMA_F16(c[mi][ni][0], c[mi][ni][1], c[mi][ni][2], c[mi][ni][3],
                            a[mi][0], a[mi][1], a[mi][2], a[mi][3],
                            b[ni][0], b[ni][1]);
        }
    }
#undef GH_LOAD

#pragma unroll
    for (int mi = 0; mi < 4; mi++) {
#pragma unroll
        for (int ni = 0; ni < 4; ni++) {
            int m = m0 + wm + mi * 16 + g;
            int n = ncol0 + wn + ni * 8 + 2 * t;
            float v00 = c[mi][ni][0], v01 = c[mi][ni][1];
            float v10 = c[mi][ni][2], v11 = c[mi][ni][3];
            if (mode == 1) {
                float2 a0 = __half22float2(*(const __half2*)(Add + (size_t)m * 512 + n));
                float2 a1 = __half22float2(*(const __half2*)(Add + (size_t)(m + 8) * 512 + n));
                v00 += a0.x; v01 += a0.y; v10 += a1.x; v11 += a1.y;
            } else if (mode == 2) {
                float2 bb = *(const float2*)(bias + n);
                v00 += bb.x; v01 += bb.y; v10 += bb.x; v11 += bb.y;
            }
            *(__half2*)(Cout + (size_t)m * 512 + n) = __floats2half2_rn(v00, v01);
            *(__half2*)(Cout + (size_t)(m + 8) * 512 + n) = __floats2half2_rn(v10, v11);
        }
    }
}

// ---------------------------------------------------------------------------
// fp16 tensor-core attention (validated): block per (n,head), 192 threads,
// occ 4; V aliases K when Kg==Vg.
// ---------------------------------------------------------------------------
__global__ __launch_bounds__(192, 4) void attn_h(
    const __half* __restrict__ Qg, const __half* __restrict__ Kg,
    const __half* __restrict__ Vg, __half* __restrict__ Og)
{
    extern __shared__ char smc[];
    unsigned sq = (unsigned)__cvta_generic_to_shared(smc);     // Q [96][72]
    unsigned sk = sq + 96 * 72 * 2;                            // K [96][72]
    unsigned sv0 = sk + 96 * 72 * 2;                           // V [96][72]

    int hd = blockIdx.x, n = blockIdx.y;
    size_t base = (size_t)n * 96 * 512 + hd * 64;
    int tid = threadIdx.x;
    int w = tid >> 5, l = tid & 31;
    int g = l >> 2, t = l & 3;
    int qr = w * 16;
    int p = l & 7, sel = l >> 3;

    bool kv_same = (Kg == Vg);
    unsigned sv = kv_same ? sk : sv0;

    for (int i = tid; i < 768; i += 192) {
        int r = i >> 3;
        unsigned d = (unsigned)((r * 72 + (i & 7) * 8) * 2);
        size_t goff = base + (size_t)r * 512 + (i & 7) * 8;
        CP16(sq + d, Qg + goff);
        CP16(sk + d, Kg + goff);
        if (!kv_same) CP16(sv0 + d, Vg + goff);
    }
    CP_COMMIT();
    CP_WAIT0();
    __syncthreads();

    float c[12][4];
#pragma unroll
    for (int ni = 0; ni < 12; ni++)
#pragma unroll
        for (int r = 0; r < 4; r++) c[ni][r] = 0.f;

    unsigned aq_off = (unsigned)(((qr + p + (sel & 1) * 8) * 72 + (sel >> 1) * 8) * 2);
    unsigned bk_off = (unsigned)(((p + (sel & 1) * 8) * 72 + (sel >> 1) * 8) * 2);

#pragma unroll
    for (int ks = 0; ks < 4; ks++) {
        unsigned kofs = (unsigned)(ks * 32);
        unsigned a0, a1, a2, a3;
        LDSM_X4(a0, a1, a2, a3, sq + aq_off + kofs);
#pragma unroll
        for (int nj = 0; nj < 6; nj++) {
            unsigned addr = sk + bk_off + (unsigned)(nj * 16 * 144) + kofs;
            unsigned q0, q1, q2, q3;
            LDSM_X4(q0, q1, q2, q3, addr);
            MMA_F16(c[2*nj][0], c[2*nj][1], c[2*nj][2], c[2*nj][3],
                    a0, a1, a2, a3, q0, q2);
            MMA_F16(c[2*nj+1][0], c[2*nj+1][1], c[2*nj+1][2], c[2*nj+1][3],
                    a0, a1, a2, a3, q1, q3);
        }
    }

    float m0 = -1e30f, m1 = -1e30f;
#pragma unroll
    for (int ni = 0; ni < 12; ni++) {
#pragma unroll
        for (int r = 0; r < 4; r++) c[ni][r] *= 0.125f;
        m0 = fmaxf(m0, fmaxf(c[ni][0], c[ni][1]));
        m1 = fmaxf(m1, fmaxf(c[ni][2], c[ni][3]));
    }
    m0 = fmaxf(m0, __shfl_xor_sync(0xffffffff, m0, 1));
    m0 = fmaxf(m0, __shfl_xor_sync(0xffffffff, m0, 2));
    m1 = fmaxf(m1, __shfl_xor_sync(0xffffffff, m1, 1));
    m1 = fmaxf(m1, __shfl_xor_sync(0xffffffff, m1, 2));
    float s0 = 0.f, s1 = 0.f;
#pragma unroll
    for (int ni = 0; ni < 12; ni++) {
        c[ni][0] = fast_exp(c[ni][0] - m0);
        c[ni][1] = fast_exp(c[ni][1] - m0);
        c[ni][2] = fast_exp(c[ni][2] - m1);
        c[ni][3] = fast_exp(c[ni][3] - m1);
        s0 += c[ni][0] + c[ni][1];
        s1 += c[ni][2] + c[ni][3];
    }
    s0 += __shfl_xor_sync(0xffffffff, s0, 1);
    s0 += __shfl_xor_sync(0xffffffff, s0, 2);
    s1 += __shfl_xor_sync(0xffffffff, s1, 1);
    s1 += __shfl_xor_sync(0xffffffff, s1, 2);

    unsigned ph[24];
#pragma unroll
    for (int ni = 0; ni < 12; ni++) {
        ph[2 * ni]     = h2pack(c[ni][0], c[ni][1]);
        ph[2 * ni + 1] = h2pack(c[ni][2], c[ni][3]);
    }

    float o[8][4];
#pragma unroll
    for (int ni = 0; ni < 8; ni++)
#pragma unroll
        for (int r = 0; r < 4; r++) o[ni][r] = 0.f;

    unsigned bv_off = (unsigned)(((p + (sel & 1) * 8) * 72 + (sel >> 1) * 8) * 2);
#pragma unroll
    for (int ks = 0; ks < 6; ks++) {
        unsigned a0 = ph[4 * ks + 0];
        unsigned a1 = ph[4 * ks + 1];
        unsigned a2 = ph[4 * ks + 2];
        unsigned a3 = ph[4 * ks + 3];
#pragma unroll
        for (int nj = 0; nj < 4; nj++) {
            unsigned addr = sv + bv_off + (unsigned)(ks * 16 * 144 + nj * 32);
            unsigned q0, q1, q2, q3;
            LDSM_X4T(q0, q1, q2, q3, addr);
            MMA_F16(o[2*nj][0], o[2*nj][1], o[2*nj][2], o[2*nj][3],
                    a0, a1, a2, a3, q0, q1);
            MMA_F16(o[2*nj+1][0], o[2*nj+1][1], o[2*nj+1][2], o[2*nj+1][3],
                    a0, a1, a2, a3, q2, q3);
        }
    }

    float inv0 = 1.0f / s0, inv1 = 1.0f / s1;
    __half* ob = Og + base;
#pragma unroll
    for (int ni = 0; ni < 8; ni++) {
        *(__half2*)(ob + (size_t)(qr + g) * 512 + ni * 8 + 2 * t) =
            __floats2half2_rn(o[ni][0] * inv0, o[ni][1] * inv0);
        *(__half2*)(ob + (size_t)(qr + g + 8) * 512 + ni * 8 + 2 * t) =
            __floats2half2_rn(o[ni][2] * inv1, o[ni][3] * inv1);
    }
}

// ---------------------------------------------------------------------------
__global__ void bnprep(const float* __restrict__ g, const float* __restrict__ b,
                       const float* __restrict__ m, const float* __restrict__ v) {
    int c = blockIdx.x * 256 + threadIdx.x;
    if (c < 512) {
        float sc = g[c] * rsqrtf(v[c] + 1e-5f);
        g_bnscale[c] = sc;
        g_bnbias[c]  = b[c] - m[c] * sc;
    }
}

__global__ void dwconv_bn(const float* __restrict__ x, const float* __restrict__ wd,
                          __half* __restrict__ o) {
    int idx = blockIdx.x * 256 + threadIdx.x;
    int wg = idx % 24;
    int t = idx / 24;
    int h = t % 96;
    int bc = t / 96;
    int c = bc & 511;
    int w0 = wg * 4;
    const float* wt = wd + c * 9;
    const float* xp = x + (size_t)bc * 9216;
    float acc[4] = {0.f, 0.f, 0.f, 0.f};
#pragma unroll
    for (int kh = 0; kh < 3; kh++) {
        int hh = h + kh - 1;
        if (hh < 0 || hh >= 96) continue;
        const float* row = xp + hh * 96;
        float4 v = *(const float4*)(row + w0);
        float left  = (w0 > 0)  ? row[w0 - 1] : 0.f;
        float right = (w0 < 92) ? row[w0 + 4] : 0.f;
        float vals[6] = {left, v.x, v.y, v.z, v.w, right};
        float wa = wt[kh * 3 + 0], wb = wt[kh * 3 + 1], wc = wt[kh * 3 + 2];
#pragma unroll
        for (int j = 0; j < 4; j++)
            acc[j] = fmaf(vals[j], wa, fmaf(vals[j + 1], wb, fmaf(vals[j + 2], wc, acc[j])));
    }
    float sc = g_bnscale[c], bb = g_bnbias[c];
    __half* op = o + (size_t)bc * 9216 + h * 96 + w0;
    *(__half2*)op       = __floats2half2_rn(fmaf(acc[0], sc, bb), fmaf(acc[1], sc, bb));
    *(__half2*)(op + 2) = __floats2half2_rn(fmaf(acc[2], sc, bb), fmaf(acc[3], sc, bb));
}

// ---------------------------------------------------------------------------
// fp16 1x1-conv GEMM per batch: Out = clip(pw@y, 0, 6) + CR (CR in half,
// image layout — same flat indexing as Out, coalesced half2 reads)
// ---------------------------------------------------------------------------
__global__ __launch_bounds__(256, 2) void gemm_conv_h(
    const __half* __restrict__ Apw, const __half* __restrict__ Bt,
    const __half* __restrict__ CR, float* __restrict__ Out)
{
    extern __shared__ char smc[];
    __half* As = (__half*)smc;
    __half* Bs = (__half*)(smc + 36864);
    int bat = blockIdx.z;
    size_t boff = (size_t)bat * 512 * 9216;
    const __half* Bg = Bt + boff;
    int n0 = blockIdx.x * 128;
    int m0 = blockIdx.y * 128;
    int tid = threadIdx.x;
    int w = tid >> 5, l = tid & 31;
    int g = l >> 2, t = l & 3;
    int wm = (w & 1) * 64, wn = (w >> 1) * 32;

    int uA = tid & 7, rA = tid >> 3;
    int uB = tid & 15, rB = tid >> 4;

    unsigned sa = (unsigned)__cvta_generic_to_shared(As);
    unsigned sb = (unsigned)__cvta_generic_to_shared(Bs);
    int p = l & 7, sel = l >> 3;
    unsigned a_off = (unsigned)(((wm + p + (sel & 1) * 8) * 72 + (sel >> 1) * 8) * 2);
    unsigned b_off = (unsigned)(((p + (sel & 1) * 8) * 136 + (sel >> 1) * 8) * 2);

    float c[4][4][4];
#pragma unroll
    for (int mi = 0; mi < 4; mi++)
#pragma unroll
        for (int ni = 0; ni < 4; ni++)
#pragma unroll
            for (int r = 0; r < 4; r++) c[mi][ni][r] = 0.f;

#define GC_LOAD(st, kc) do { \
    const __half* Ag = Apw + (size_t)(m0 + rA) * 512 + (kc) * 64 + uA * 8; \
    unsigned da = sa + (unsigned)(((st) * 9216 + rA * 72 + uA * 8) * 2); \
    _Pragma("unroll") \
    for (int i = 0; i < 4; i++) \
        CP16(da + (unsigned)(i * 32 * 144), Ag + (size_t)i * 32 * 512); \
    const __half* Bgp = Bg + (size_t)((kc) * 64 + rB) * 9216 + n0 + uB * 8; \
    unsigned db = sb + (unsigned)(((st) * 8704 + rB * 136 + uB * 8) * 2); \
    _Pragma("unroll") \
    for (int i = 0; i < 4; i++) \
        CP16(db + (unsigned)(i * 16 * 272), Bgp + (size_t)i * 16 * 9216); \
    CP_COMMIT(); } while (0)

    GC_LOAD(0, 0);
#pragma unroll 1
    for (int kt = 0; kt < 8; kt++) {
        int cur = kt & 1;
        CP_WAIT0();
        __syncthreads();
        if (kt < 7) GC_LOAD(cur ^ 1, kt + 1);
        unsigned abase = sa + (unsigned)(cur * 9216 * 2) + a_off;
        unsigned bbase = sb + (unsigned)(cur * 8704 * 2) + b_off;
#pragma unroll
        for (int ks = 0; ks < 4; ks++) {
            int k0 = ks * 16;
            unsigned a[4][4];
#pragma unroll
            for (int mi = 0; mi < 4; mi++) {
                unsigned addr = abase + (unsigned)((mi * 16 * 72 + k0) * 2);
                LDSM_X4(a[mi][0], a[mi][1], a[mi][2], a[mi][3], addr);
            }
            unsigned b[4][2];
#pragma unroll
            for (int nj = 0; nj < 2; nj++) {
                unsigned addr = bbase + (unsigned)((k0 * 136 + wn + nj * 16) * 2);
                unsigned q0, q1, q2, q3;
                LDSM_X4T(q0, q1, q2, q3, addr);
                b[nj * 2][0] = q0;     b[nj * 2][1] = q1;
                b[nj * 2 + 1][0] = q2; b[nj * 2 + 1][1] = q3;
            }
#pragma unroll
            for (int mi = 0; mi < 4; mi++)
#pragma unroll
                for (int ni = 0; ni < 4; ni++)
                    MMA_F16(c[mi][ni][0], c[mi][ni][1], c[mi][ni][2], c[mi][ni][3],
                            a[mi][0], a[mi][1], a[mi][2], a[mi][3],
                            b[ni][0], b[ni][1]);
        }
        __syncthreads();
    }
#undef GC_LOAD

#pragma unroll
    for (int mi = 0; mi < 4; mi++) {
#pragma unroll
        for (int ni = 0; ni < 4; ni++) {
            int m = m0 + wm + mi * 16 + g;
            int n = n0 + wn + ni * 8 + 2 * t;
            size_t off0 = boff + (size_t)m * 9216 + n;
            size_t off1 = boff + (size_t)(m + 8) * 9216 + n;
            float2 cr0 = __half22float2(*(const __half2*)(CR + off0));
            float2 cr1 = __half22float2(*(const __half2*)(CR + off1));
            float2 o0, o1;
            o0.x = fminf(fmaxf(c[mi][ni][0], 0.f), 6.f) + cr0.x;
            o0.y = fminf(fmaxf(c[mi][ni][1], 0.f), 6.f) + cr0.y;
            o1.x = fminf(fmaxf(c[mi][ni][2], 0.f), 6.f) + cr1.x;
            o1.y = fminf(fmaxf(c[mi][ni][3], 0.f), 6.f) + cr1.y;
            *(float2*)(Out + off0) = o0;
            *(float2*)(Out + off1) = o1;
        }
    }
}

// ---------------------------------------------------------------------------
// Host launch — R9 schedule (prep-only on s2; all compute serial on main),
// cr kept in half image layout (h4) and added in the conv epilogue.
// ---------------------------------------------------------------------------
extern "C" void kernel_launch(void* const* d_in, const int* in_sizes, int n_in,
                              void* d_out, int out_size) {
    const float* x   = (const float*)d_in[0];
    const float* Wk  = (const float*)d_in[1];
    const float* Wv  = (const float*)d_in[2];
    const float* Wo  = (const float*)d_in[3];
    const float* cWq = (const float*)d_in[4];
    const float* cbq = (const float*)d_in[5];
    const float* cWv = (const float*)d_in[6];
    const float* cWo = (const float*)d_in[7];
    const float* dww = (const float*)d_in[8];
    const float* bng = (const float*)d_in[9];
    const float* bnb = (const float*)d_in[10];
    const float* bnm = (const float*)d_in[11];
    const float* bnv = (const float*)d_in[12];
    const float* pww = (const float*)d_in[13];
    float* out = (float*)d_out;

    __half* hb = nullptr;
    cudaGetSymbolAddress((void**)&hb, g_hb);
    __half* h0 = hb + (size_t)0 * TOTE;
    __half* h1 = hb + (size_t)1 * TOTE;
    __half* h2 = hb + (size_t)2 * TOTE;
    __half* h3 = hb + (size_t)3 * TOTE;
    __half* h4 = hb + (size_t)4 * TOTE;
    __half* dwh = nullptr;
    cudaGetSymbolAddress((void**)&dwh, g_dwh);
    __half* wh = nullptr;
    cudaGetSymbolAddress((void**)&wh, g_wh);
    __half* wKVV = wh;                              // slots 0..2 contiguous
    __half* rWo  = wh + (size_t)3 * 262144;
    __half* rcWq = wh + (size_t)4 * 262144;
    __half* rcWo = wh + (size_t)5 * 262144;
    __half* rpw  = wh + (size_t)6 * 262144;

    const int GEMM_SMEM = 8 * 5120 * 2;             // 81920
    const int CONV_SMEM = (2 * 9216 + 2 * 8704) * 2;
    const int ATTN_SMEM = 3 * 96 * 72 * 2;          // 41472
    cudaFuncSetAttribute(gemm_h, cudaFuncAttributeMaxDynamicSharedMemorySize, GEMM_SMEM);
    cudaFuncSetAttribute(gemm_conv_h, cudaFuncAttributeMaxDynamicSharedMemorySize, CONV_SMEM);
    cudaFuncSetAttribute(attn_h, cudaFuncAttributeMaxDynamicSharedMemorySize, ATTN_SMEM);

    // Side stream + events: created once, host-side, outside any capture.
    static cudaStream_t s2 = nullptr;
    static cudaEvent_t evFork = nullptr, evW = nullptr, evDw = nullptr;
    if (!s2) {
        cudaStreamCreateWithFlags(&s2, cudaStreamNonBlocking);
        cudaEventCreateWithFlags(&evFork, cudaEventDisableTiming);
        cudaEventCreateWithFlags(&evW, cudaEventDisableTiming);
        cudaEventCreateWithFlags(&evDw, cudaEventDisableTiming);
    }

    dim3 tgT(3, 8, 768);            // 64c x 32w tiles
    dim3 tbI(32, 16);               // img2seq
    dim3 tbS(64, 8);                // seq2img_hh

    // ---- fork: weight prep + dwconv on s2 (cheap, overlaps img2seq/QKV) ----
    cudaEventRecord(evFork, 0);
    cudaStreamWaitEvent(s2, evFork, 0);
    wprep<<<1792, 256, 0, s2>>>(Wk, Wv, cWv, Wo, cWq, cWo, pww);
    cudaEventRecord(evW, s2);
    bnprep<<<2, 256, 0, s2>>>(bng, bnb, bnm, bnv);
    dwconv_bn<<<36864, 256, 0, s2>>>(x, dww, dwh);
    cudaEventRecord(evDw, s2);

    // ---- main chain (all compute serial here) ----
    img2seq<<<tgT, tbI>>>(x, h0);
    cudaStreamWaitEvent(0, evW, 0);   // weights ready
    gemm_h<<<dim3(12, 576), 256, GEMM_SMEM>>>(h0, wKVV, h0, nullptr, h1, h2, h3, 1, 0, 0);
    attn_h<<<dim3(8, 768), 192, ATTN_SMEM>>>(h0, h1, h2, h4);
    gemm_h<<<dim3(4, 576), 256, GEMM_SMEM>>>(h4, rWo, nullptr, nullptr, h1, h1, h1, 0, 0, 0);
    seq2img_hh<<<tgT, tbS>>>(h1, h2);
    gemm_h<<<dim3(4, 576), 256, GEMM_SMEM>>>(h2, rcWq, nullptr, cbq, h4, h4, h4, 2, 2, 2);
    attn_h<<<dim3(8, 768), 192, ATTN_SMEM>>>(h4, h3, h3, h1);
    gemm_h<<<dim3(4, 576), 256, GEMM_SMEM>>>(h1, rcWo, nullptr, nullptr, h2, h2, h2, 0, 0, 0);
    seq2img_hh<<<tgT, tbS>>>(h2, h4);   // cr -> half image layout
    cudaStreamWaitEvent(0, evDw, 0);    // dwconv output ready
    gemm_conv_h<<<dim3(72, 4, 8), 256, CONV_SMEM>>>(rpw, dwh, h4, out);
}

// round 16
// speedup vs baseline: 1.0086x; 1.0086x over previous
#include <cuda_runtime.h>
#include <cuda_fp16.h>
#include <math.h>
#include <cstdint>

// ---------------------------------------------------------------------------
// Problem constants: B=8, C=512, H=W=96, heads=8, dh=64
// seq layout: [768, 96, 512]  (n = b*96 + w, t = h, channel c)
// ---------------------------------------------------------------------------
#define TOTE 37748736  // 768*96*512

__device__ __half g_hb[5][TOTE];     // fp16 activation buffers
__device__ __half g_dwh[TOTE];       // dwconv output (separate so it can overlap)
__device__ __half g_wh[7 * 262144];  // fp16 weights: Wk,Wv,cWv,Wo,cWq,cWo,pw
__device__ float  g_bnscale[512];
__device__ float  g_bnbias[512];

__device__ __forceinline__ float fast_exp(float x) {
    x = fmaxf(x, -87.0f);
    float t = x * 1.44269504088896f;
    float fi = floorf(t);
    float f = t - fi;
    float p = 1.54035304e-4f;
    p = fmaf(p, f, 1.33335581e-3f);
    p = fmaf(p, f, 9.61812910e-3f);
    p = fmaf(p, f, 5.55041087e-2f);
    p = fmaf(p, f, 2.40226507e-1f);
    p = fmaf(p, f, 6.93147181e-1f);
    p = fmaf(p, f, 1.0f);
    return p * __int_as_float(((int)fi + 127) << 23);
}

#define MMA_F16(c0,c1,c2,c3,a0,a1,a2,a3,b0,b1) \
    asm volatile("mma.sync.aligned.m16n8k16.row.col.f32.f16.f16.f32 " \
                 "{%0,%1,%2,%3},{%4,%5,%6,%7},{%8,%9},{%0,%1,%2,%3};" \
                 : "+f"(c0),"+f"(c1),"+f"(c2),"+f"(c3) \
                 : "r"(a0),"r"(a1),"r"(a2),"r"(a3),"r"(b0),"r"(b1))

#define LDSM_X4(r0,r1,r2,r3,addr) \
    asm volatile("ldmatrix.sync.aligned.m8n8.x4.shared.b16 {%0,%1,%2,%3}, [%4];" \
                 : "=r"(r0),"=r"(r1),"=r"(r2),"=r"(r3) : "r"(addr))

#define LDSM_X4T(r0,r1,r2,r3,addr) \
    asm volatile("ldmatrix.sync.aligned.m8n8.x4.trans.shared.b16 {%0,%1,%2,%3}, [%4];" \
                 : "=r"(r0),"=r"(r1),"=r"(r2),"=r"(r3) : "r"(addr))

#define CP16(dst, src) \
    asm volatile("cp.async.cg.shared.global [%0], [%1], 16;" :: "r"(dst), "l"(src))
#define CP_COMMIT() asm volatile("cp.async.commit_group;")
#define CP_WAIT0()  asm volatile("cp.async.wait_group 0;")
#define CP_WAIT3()  asm volatile("cp.async.wait_group 3;")

__device__ __forceinline__ unsigned h2pack(float a, float b) {
    unsigned r;
    asm("cvt.rn.f16x2.f32 %0, %2, %1;" : "=r"(r) : "f"(a), "f"(b));
    return r;
}

// ---------------------------------------------------------------------------
// Weight prep: fp16-round 7 [512x512] matrices into g_wh (slot order = arg order)
// ---------------------------------------------------------------------------
__global__ void wprep(const float* __restrict__ a0, const float* __restrict__ a1,
                      const float* __restrict__ a2, const float* __restrict__ a3,
                      const float* __restrict__ a4, const float* __restrict__ a5,
                      const float* __restrict__ a6) {
    int i = blockIdx.x * 256 + threadIdx.x;
    int mat = i >> 16;
    int off = (i & 65535) * 4;
    const float* s;
    switch (mat) {
        case 0: s = a0; break; case 1: s = a1; break; case 2: s = a2; break;
        case 3: s = a3; break; case 4: s = a4; break; case 5: s = a5; break;
        default: s = a6; break;
    }
    float4 v = *(const float4*)(s + off);
    *(__half2*)(g_wh + (size_t)mat * 262144 + off)     = __floats2half2_rn(v.x, v.y);
    *(__half2*)(g_wh + (size_t)mat * 262144 + off + 2) = __floats2half2_rn(v.z, v.w);
}

// ---------------------------------------------------------------------------
// Layout transposes (c <-> w per (b,h) plane) — R14 validated 32x32 tiles
// ---------------------------------------------------------------------------
__global__ void img2seq(const float* __restrict__ img, __half* __restrict__ seq) {
    __shared__ float tile[32][33];
    int bh = blockIdx.z;
    int b = bh / 96, h = bh % 96;
    int c0 = blockIdx.y * 32, w0 = blockIdx.x * 32;
    int tx = threadIdx.x, ty = threadIdx.y;
#pragma unroll
    for (int i = 0; i < 4; i++) {
        int c = c0 + ty + i * 8;
        tile[ty + i * 8][tx] = img[(((size_t)b * 512 + c) * 96 + h) * 96 + w0 + tx];
    }
    __syncthreads();
#pragma unroll
    for (int i = 0; i < 4; i++) {
        int w = w0 + ty + i * 8;
        seq[(((size_t)(b * 96 + w)) * 96 + h) * 512 + c0 + tx] =
            __float2half_rn(tile[tx][ty + i * 8]);
    }
}

__global__ void seq2img_hh(const __half* __restrict__ seq, __half* __restrict__ img) {
    __shared__ __half tile[32][33];
    int bh = blockIdx.z;
    int b = bh / 96, h = bh % 96;
    int c0 = blockIdx.y * 32, w0 = blockIdx.x * 32;
    int tx = threadIdx.x, ty = threadIdx.y;
#pragma unroll
    for (int i = 0; i < 4; i++) {
        int w = w0 + ty + i * 8;
        tile[ty + i * 8][tx] = seq[(((size_t)(b * 96 + w)) * 96 + h) * 512 + c0 + tx];
    }
    __syncthreads();
#pragma unroll
    for (int i = 0; i < 4; i++) {
        int c = c0 + ty + i * 8;
        img[(((size_t)b * 512 + c) * 96 + h) * 96 + w0 + tx] = tile[tx][ty + i * 8];
    }
}

// ---------------------------------------------------------------------------
// fp16 GEMM, multi-output: 128x128 tile, k-chunk 32, 5-stage cp.async
// (wait_group 3, prefetch distance 4), 256 threads, occupancy 2.
// smem: A[5][128*40]h + W[5][128*40]h = 102400B.
// ---------------------------------------------------------------------------
__global__ __launch_bounds__(256, 2) void gemm_h(
    const __half* __restrict__ A, const __half* __restrict__ Wb,
    const __half* __restrict__ Add, const float* __restrict__ bias,
    __half* __restrict__ o0, __half* __restrict__ o1, __half* __restrict__ o2,
    int mode0, int mode1, int mode2)
{
    extern __shared__ char smc[];
    unsigned sa = (unsigned)__cvta_generic_to_shared(smc);
    unsigned sw = sa + 51200;          // 5 stages x 5120 halves x 2B
    int m0 = blockIdx.y * 128;
    int nmat = blockIdx.x >> 2;
    int ncol0 = (blockIdx.x & 3) * 128;
    const __half* Wp = Wb + (size_t)blockIdx.x * 128 * 512;
    __half* Cout; int mode;
    if (nmat == 0)      { Cout = o0; mode = mode0; }
    else if (nmat == 1) { Cout = o1; mode = mode1; }
    else                { Cout = o2; mode = mode2; }

    int tid = threadIdx.x;
    int w = tid >> 5, l = tid & 31;
    int g = l >> 2, t = l & 3;
    int wm = (w & 1) * 64, wn = (w >> 1) * 32;
    int u = tid & 3, r0 = tid >> 2;    // 16B chunk, row 0..63

    int p = l & 7, sel = l >> 3;
    unsigned a_off = (unsigned)(((wm + p + (sel & 1) * 8) * 40 + (sel >> 1) * 8) * 2);
    unsigned b_off = (unsigned)(((p + (sel & 1) * 8) * 40 + (sel >> 1) * 8) * 2);

    float c[4][4][4];
#pragma unroll
    for (int mi = 0; mi < 4; mi++)
#pragma unroll
        for (int ni = 0; ni < 4; ni++)
#pragma unroll
            for (int r = 0; r < 4; r++) c[mi][ni][r] = 0.f;

#define GH_LOAD(st, kc) do { \
    const __half* Ag = A  + (size_t)(m0 + r0) * 512 + (kc) * 32 + u * 8; \
    const __half* Wg = Wp + (size_t)r0 * 512 + (kc) * 32 + u * 8; \
    unsigned da = sa + (unsigned)((st) * 10240 + (r0 * 40 + u * 8) * 2); \
    unsigned dw = sw + (unsigned)((st) * 10240 + (r0 * 40 + u * 8) * 2); \
    CP16(da, Ag); CP16(da + 5120, Ag + (size_t)64 * 512); \
    CP16(dw, Wg); CP16(dw + 5120, Wg + (size_t)64 * 512); \
    CP_COMMIT(); } while (0)

    GH_LOAD(0, 0); GH_LOAD(1, 1); GH_LOAD(2, 2); GH_LOAD(3, 3);
    int cur = 0;
#pragma unroll 1
    for (int kt = 0; kt < 16; kt++) {
        CP_WAIT3();
        __syncthreads();
        if (kt < 12) {
            int ns = cur + 4; if (ns >= 5) ns -= 5;
            GH_LOAD(ns, kt + 4);
        } else {
            CP_COMMIT();
        }
        unsigned cb = (unsigned)(cur * 10240);
#pragma unroll
        for (int ks = 0; ks < 2; ks++) {
            unsigned kofs = (unsigned)(ks * 32);
            unsigned a[4][4];
#pragma unroll
            for (int mi = 0; mi < 4; mi++) {
                unsigned addr = sa + cb + a_off + (unsigned)(mi * 16 * 80) + kofs;
                LDSM_X4(a[mi][0], a[mi][1], a[mi][2], a[mi][3], addr);
            }
            unsigned b[4][2];
#pragma unroll
            for (int nj = 0; nj < 2; nj++) {
                unsigned addr = sw + cb + b_off + (unsigned)((wn + nj * 16) * 80) + kofs;
                unsigned q0, q1, q2, q3;
                LDSM_X4(q0, q1, q2, q3, addr);
                b[nj * 2][0] = q0;     b[nj * 2][1] = q2;
                b[nj * 2 + 1][0] = q1; b[nj * 2 + 1][1] = q3;
            }
#pragma unroll
            for (int mi = 0; mi < 4; mi++)
#pragma unroll
                for (int ni = 0; ni < 4; ni++)
                    MMA_F16(c[mi][ni][0], c[mi][ni][1], c[mi][ni][2], c[mi][ni][3],
                            a[mi][0], a[mi][1], a[mi][2], a[mi][3],
                            b[ni][0], b[ni][1]);
        }
        cur = (cur == 4) ? 0 : cur + 1;
    }
#undef GH_LOAD

#pragma unroll
    for (int mi = 0; mi < 4; mi++) {
#pragma unroll
        for (int ni = 0; ni < 4; ni++) {
            int m = m0 + wm + mi * 16 + g;
            int n = ncol0 + wn + ni * 8 + 2 * t;
            float v00 = c[mi][ni][0], v01 = c[mi][ni][1];
            float v10 = c[mi][ni][2], v11 = c[mi][ni][3];
            if (mode == 1) {
                float2 a0 = __half22float2(*(const __half2*)(Add + (size_t)m * 512 + n));
                float2 a1 = __half22float2(*(const __half2*)(Add + (size_t)(m + 8) * 512 + n));
                v00 += a0.x; v01 += a0.y; v10 += a1.x; v11 += a1.y;
            } else if (mode == 2) {
                float2 bb = *(const float2*)(bias + n);
                v00 += bb.x; v01 += bb.y; v10 += bb.x; v11 += bb.y;
            }
            *(__half2*)(Cout + (size_t)m * 512 + n) = __floats2half2_rn(v00, v01);
            *(__half2*)(Cout + (size_t)(m + 8) * 512 + n) = __floats2half2_rn(v10, v11);
        }
    }
}

// ---------------------------------------------------------------------------
// fp16 tensor-core attention (validated): block per (n,head), 192 threads,
// occ 4; V aliases K when Kg==Vg.
// ---------------------------------------------------------------------------
__global__ __launch_bounds__(192, 4) void attn_h(
    const __half* __restrict__ Qg, const __half* __restrict__ Kg,
    const __half* __restrict__ Vg, __half* __restrict__ Og)
{
    extern __shared__ char smc[];
    unsigned sq = (unsigned)__cvta_generic_to_shared(smc);     // Q [96][72]
    unsigned sk = sq + 96 * 72 * 2;                            // K [96][72]
    unsigned sv0 = sk + 96 * 72 * 2;                           // V [96][72]

    int hd = blockIdx.x, n = blockIdx.y;
    size_t base = (size_t)n * 96 * 512 + hd * 64;
    int tid = threadIdx.x;
    int w = tid >> 5, l = tid & 31;
    int g = l >> 2, t = l & 3;
    int qr = w * 16;
    int p = l & 7, sel = l >> 3;

    bool kv_same = (Kg == Vg);
    unsigned sv = kv_same ? sk : sv0;

    for (int i = tid; i < 768; i += 192) {
        int r = i >> 3;
        unsigned d = (unsigned)((r * 72 + (i & 7) * 8) * 2);
        size_t goff = base + (size_t)r * 512 + (i & 7) * 8;
        CP16(sq + d, Qg + goff);
        CP16(sk + d, Kg + goff);
        if (!kv_same) CP16(sv0 + d, Vg + goff);
    }
    CP_COMMIT();
    CP_WAIT0();
    __syncthreads();

    float c[12][4];
#pragma unroll
    for (int ni = 0; ni < 12; ni++)
#pragma unroll
        for (int r = 0; r < 4; r++) c[ni][r] = 0.f;

    unsigned aq_off = (unsigned)(((qr + p + (sel & 1) * 8) * 72 + (sel >> 1) * 8) * 2);
    unsigned bk_off = (unsigned)(((p + (sel & 1) * 8) * 72 + (sel >> 1) * 8) * 2);

#pragma unroll
    for (int ks = 0; ks < 4; ks++) {
        unsigned kofs = (unsigned)(ks * 32);
        unsigned a0, a1, a2, a3;
        LDSM_X4(a0, a1, a2, a3, sq + aq_off + kofs);
#pragma unroll
        for (int nj = 0; nj < 6; nj++) {
            unsigned addr = sk + bk_off + (unsigned)(nj * 16 * 144) + kofs;
            unsigned q0, q1, q2, q3;
            LDSM_X4(q0, q1, q2, q3, addr);
            MMA_F16(c[2*nj][0], c[2*nj][1], c[2*nj][2], c[2*nj][3],
                    a0, a1, a2, a3, q0, q2);
            MMA_F16(c[2*nj+1][0], c[2*nj+1][1], c[2*nj+1][2], c[2*nj+1][3],
                    a0, a1, a2, a3, q1, q3);
        }
    }

    float m0 = -1e30f, m1 = -1e30f;
#pragma unroll
    for (int ni = 0; ni < 12; ni++) {
#pragma unroll
        for (int r = 0; r < 4; r++) c[ni][r] *= 0.125f;
        m0 = fmaxf(m0, fmaxf(c[ni][0], c[ni][1]));
        m1 = fmaxf(m1, fmaxf(c[ni][2], c[ni][3]));
    }
    m0 = fmaxf(m0, __shfl_xor_sync(0xffffffff, m0, 1));
    m0 = fmaxf(m0, __shfl_xor_sync(0xffffffff, m0, 2));
    m1 = fmaxf(m1, __shfl_xor_sync(0xffffffff, m1, 1));
    m1 = fmaxf(m1, __shfl_xor_sync(0xffffffff, m1, 2));
    float s0 = 0.f, s1 = 0.f;
#pragma unroll
    for (int ni = 0; ni < 12; ni++) {
        c[ni][0] = fast_exp(c[ni][0] - m0);
        c[ni][1] = fast_exp(c[ni][1] - m0);
        c[ni][2] = fast_exp(c[ni][2] - m1);
        c[ni][3] = fast_exp(c[ni][3] - m1);
        s0 += c[ni][0] + c[ni][1];
        s1 += c[ni][2] + c[ni][3];
    }
    s0 += __shfl_xor_sync(0xffffffff, s0, 1);
    s0 += __shfl_xor_sync(0xffffffff, s0, 2);
    s1 += __shfl_xor_sync(0xffffffff, s1, 1);
    s1 += __shfl_xor_sync(0xffffffff, s1, 2);

    unsigned ph[24];
#pragma unroll
    for (int ni = 0; ni < 12; ni++) {
        ph[2 * ni]     = h2pack(c[ni][0], c[ni][1]);
        ph[2 * ni + 1] = h2pack(c[ni][2], c[ni][3]);
    }

    float o[8][4];
#pragma unroll
    for (int ni = 0; ni < 8; ni++)
#pragma unroll
        for (int r = 0; r < 4; r++) o[ni][r] = 0.f;

    unsigned bv_off = (unsigned)(((p + (sel & 1) * 8) * 72 + (sel >> 1) * 8) * 2);
#pragma unroll
    for (int ks = 0; ks < 6; ks++) {
        unsigned a0 = ph[4 * ks + 0];
        unsigned a1 = ph[4 * ks + 1];
        unsigned a2 = ph[4 * ks + 2];
        unsigned a3 = ph[4 * ks + 3];
#pragma unroll
        for (int nj = 0; nj < 4; nj++) {
            unsigned addr = sv + bv_off + (unsigned)(ks * 16 * 144 + nj * 32);
            unsigned q0, q1, q2, q3;
            LDSM_X4T(q0, q1, q2, q3, addr);
            MMA_F16(o[2*nj][0], o[2*nj][1], o[2*nj][2], o[2*nj][3],
                    a0, a1, a2, a3, q0, q1);
            MMA_F16(o[2*nj+1][0], o[2*nj+1][1], o[2*nj+1][2], o[2*nj+1][3],
                    a0, a1, a2, a3, q2, q3);
        }
    }

    float inv0 = 1.0f / s0, inv1 = 1.0f / s1;
    __half* ob = Og + base;
#pragma unroll
    for (int ni = 0; ni < 8; ni++) {
        *(__half2*)(ob + (size_t)(qr + g) * 512 + ni * 8 + 2 * t) =
            __floats2half2_rn(o[ni][0] * inv0, o[ni][1] * inv0);
        *(__half2*)(ob + (size_t)(qr + g + 8) * 512 + ni * 8 + 2 * t) =
            __floats2half2_rn(o[ni][2] * inv1, o[ni][3] * inv1);
    }
}

// ---------------------------------------------------------------------------
__global__ void bnprep(const float* __restrict__ g, const float* __restrict__ b,
                       const float* __restrict__ m, const float* __restrict__ v) {
    int c = blockIdx.x * 256 + threadIdx.x;
    if (c < 512) {
        float sc = g[c] * rsqrtf(v[c] + 1e-5f);
        g_bnscale[c] = sc;
        g_bnbias[c]  = b[c] - m[c] * sc;
    }
}

__global__ void dwconv_bn(const float* __restrict__ x, const float* __restrict__ wd,
                          __half* __restrict__ o) {
    int idx = blockIdx.x * 256 + threadIdx.x;
    int wg = idx % 24;
    int t = idx / 24;
    int h = t % 96;
    int bc = t / 96;
    int c = bc & 511;
    int w0 = wg * 4;
    const float* wt = wd + c * 9;
    const float* xp = x + (size_t)bc * 9216;
    float acc[4] = {0.f, 0.f, 0.f, 0.f};
#pragma unroll
    for (int kh = 0; kh < 3; kh++) {
        int hh = h + kh - 1;
        if (hh < 0 || hh >= 96) continue;
        const float* row = xp + hh * 96;
        float4 v = *(const float4*)(row + w0);
        float left  = (w0 > 0)  ? row[w0 - 1] : 0.f;
        float right = (w0 < 92) ? row[w0 + 4] : 0.f;
        float vals[6] = {left, v.x, v.y, v.z, v.w, right};
        float wa = wt[kh * 3 + 0], wb = wt[kh * 3 + 1], wc = wt[kh * 3 + 2];
#pragma unroll
        for (int j = 0; j < 4; j++)
            acc[j] = fmaf(vals[j], wa, fmaf(vals[j + 1], wb, fmaf(vals[j + 2], wc, acc[j])));
    }
    float sc = g_bnscale[c], bb = g_bnbias[c];
    __half* op = o + (size_t)bc * 9216 + h * 96 + w0;
    *(__half2*)op       = __floats2half2_rn(fmaf(acc[0], sc, bb), fmaf(acc[1], sc, bb));
    *(__half2*)(op + 2) = __floats2half2_rn(fmaf(acc[2], sc, bb), fmaf(acc[3], sc, bb));
}

// ---------------------------------------------------------------------------
// fp16 1x1-conv GEMM per batch: Out = clip(pw@y, 0, 6) + CR (CR in half,
// image layout — same flat indexing as Out, coalesced half2 reads)
// ---------------------------------------------------------------------------
__global__ __launch_bounds__(256, 2) void gemm_conv_h(
    const __half* __restrict__ Apw, const __half* __restrict__ Bt,
    const __half* __restrict__ CR, float* __restrict__ Out)
{
    extern __shared__ char smc[];
    __half* As = (__half*)smc;
    __half* Bs = (__half*)(smc + 36864);
    int bat = blockIdx.z;
    size_t boff = (size_t)bat * 512 * 9216;
    const __half* Bg = Bt + boff;
    int n0 = blockIdx.x * 128;
    int m0 = blockIdx.y * 128;
    int tid = threadIdx.x;
    int w = tid >> 5, l = tid & 31;
    int g = l >> 2, t = l & 3;
    int wm = (w & 1) * 64, wn = (w >> 1) * 32;

    int uA = tid & 7, rA = tid >> 3;
    int uB = tid & 15, rB = tid >> 4;

    unsigned sa = (unsigned)__cvta_generic_to_shared(As);
    unsigned sb = (unsigned)__cvta_generic_to_shared(Bs);
    int p = l & 7, sel = l >> 3;
    unsigned a_off = (unsigned)(((wm + p + (sel & 1) * 8) * 72 + (sel >> 1) * 8) * 2);
    unsigned b_off = (unsigned)(((p + (sel & 1) * 8) * 136 + (sel >> 1) * 8) * 2);

    float c[4][4][4];
#pragma unroll
    for (int mi = 0; mi < 4; mi++)
#pragma unroll
        for (int ni = 0; ni < 4; ni++)
#pragma unroll
            for (int r = 0; r < 4; r++) c[mi][ni][r] = 0.f;

#define GC_LOAD(st, kc) do { \
    const __half* Ag = Apw + (size_t)(m0 + rA) * 512 + (kc) * 64 + uA * 8; \
    unsigned da = sa + (unsigned)(((st) * 9216 + rA * 72 + uA * 8) * 2); \
    _Pragma("unroll") \
    for (int i = 0; i < 4; i++) \
        CP16(da + (unsigned)(i * 32 * 144), Ag + (size_t)i * 32 * 512); \
    const __half* Bgp = Bg + (size_t)((kc) * 64 + rB) * 9216 + n0 + uB * 8; \
    unsigned db = sb + (unsigned)(((st) * 8704 + rB * 136 + uB * 8) * 2); \
    _Pragma("unroll") \
    for (int i = 0; i < 4; i++) \
        CP16(db + (unsigned)(i * 16 * 272), Bgp + (size_t)i * 16 * 9216); \
    CP_COMMIT(); } while (0)

    GC_LOAD(0, 0);
#pragma unroll 1
    for (int kt = 0; kt < 8; kt++) {
        int cur = kt & 1;
        CP_WAIT0();
        __syncthreads();
        if (kt < 7) GC_LOAD(cur ^ 1, kt + 1);
        unsigned abase = sa + (unsigned)(cur * 9216 * 2) + a_off;
        unsigned bbase = sb + (unsigned)(cur * 8704 * 2) + b_off;
#pragma unroll
        for (int ks = 0; ks < 4; ks++) {
            int k0 = ks * 16;
            unsigned a[4][4];
#pragma unroll
            for (int mi = 0; mi < 4; mi++) {
                unsigned addr = abase + (unsigned)((mi * 16 * 72 + k0) * 2);
                LDSM_X4(a[mi][0], a[mi][1], a[mi][2], a[mi][3], addr);
            }
            unsigned b[4][2];
#pragma unroll
            for (int nj = 0; nj < 2; nj++) {
                unsigned addr = bbase + (unsigned)((k0 * 136 + wn + nj * 16) * 2);
                unsigned q0, q1, q2, q3;
                LDSM_X4T(q0, q1, q2, q3, addr);
                b[nj * 2][0] = q0;     b[nj * 2][1] = q1;
                b[nj * 2 + 1][0] = q2; b[nj * 2 + 1][1] = q3;
            }
#pragma unroll
            for (int mi = 0; mi < 4; mi++)
#pragma unroll
                for (int ni = 0; ni < 4; ni++)
                    MMA_F16(c[mi][ni][0], c[mi][ni][1], c[mi][ni][2], c[mi][ni][3],
                            a[mi][0], a[mi][1], a[mi][2], a[mi][3],
                            b[ni][0], b[ni][1]);
        }
        __syncthreads();
    }
#undef GC_LOAD

#pragma unroll
    for (int mi = 0; mi < 4; mi++) {
#pragma unroll
        for (int ni = 0; ni < 4; ni++) {
            int m = m0 + wm + mi * 16 + g;
            int n = n0 + wn + ni * 8 + 2 * t;
            size_t off0 = boff + (size_t)m * 9216 + n;
            size_t off1 = boff + (size_t)(m + 8) * 9216 + n;
            float2 cr0 = __half22float2(*(const __half2*)(CR + off0));
            float2 cr1 = __half22float2(*(const __half2*)(CR + off1));
            float2 o0, o1;
            o0.x = fminf(fmaxf(c[mi][ni][0], 0.f), 6.f) + cr0.x;
            o0.y = fminf(fmaxf(c[mi][ni][1], 0.f), 6.f) + cr0.y;
            o1.x = fminf(fmaxf(c[mi][ni][2], 0.f), 6.f) + cr1.x;
            o1.y = fminf(fmaxf(c[mi][ni][3], 0.f), 6.f) + cr1.y;
            *(float2*)(Out + off0) = o0;
            *(float2*)(Out + off1) = o1;
        }
    }
}

// ---------------------------------------------------------------------------
// Host launch — R14 schedule (prep-only on s2; all compute serial on main),
// cr kept in half image layout (h4) and added in the conv epilogue.
// ---------------------------------------------------------------------------
extern "C" void kernel_launch(void* const* d_in, const int* in_sizes, int n_in,
                              void* d_out, int out_size) {
    const float* x   = (const float*)d_in[0];
    const float* Wk  = (const float*)d_in[1];
    const float* Wv  = (const float*)d_in[2];
    const float* Wo  = (const float*)d_in[3];
    const float* cWq = (const float*)d_in[4];
    const float* cbq = (const float*)d_in[5];
    const float* cWv = (const float*)d_in[6];
    const float* cWo = (const float*)d_in[7];
    const float* dww = (const float*)d_in[8];
    const float* bng = (const float*)d_in[9];
    const float* bnb = (const float*)d_in[10];
    const float* bnm = (const float*)d_in[11];
    const float* bnv = (const float*)d_in[12];
    const float* pww = (const float*)d_in[13];
    float* out = (float*)d_out;

    __half* hb = nullptr;
    cudaGetSymbolAddress((void**)&hb, g_hb);
    __half* h0 = hb + (size_t)0 * TOTE;
    __half* h1 = hb + (size_t)1 * TOTE;
    __half* h2 = hb + (size_t)2 * TOTE;
    __half* h3 = hb + (size_t)3 * TOTE;
    __half* h4 = hb + (size_t)4 * TOTE;
    __half* dwh = nullptr;
    cudaGetSymbolAddress((void**)&dwh, g_dwh);
    __half* wh = nullptr;
    cudaGetSymbolAddress((void**)&wh, g_wh);
    __half* wKVV = wh;                              // slots 0..2 contiguous
    __half* rWo  = wh + (size_t)3 * 262144;
    __half* rcWq = wh + (size_t)4 * 262144;
    __half* rcWo = wh + (size_t)5 * 262144;
    __half* rpw  = wh + (size_t)6 * 262144;

    const int GEMM_SMEM = 10 * 5120 * 2;            // 102400 (5 stages A+W)
    const int CONV_SMEM = (2 * 9216 + 2 * 8704) * 2;
    const int ATTN_SMEM = 3 * 96 * 72 * 2;          // 41472
    cudaFuncSetAttribute(gemm_h, cudaFuncAttributeMaxDynamicSharedMemorySize, GEMM_SMEM);
    cudaFuncSetAttribute(gemm_conv_h, cudaFuncAttributeMaxDynamicSharedMemorySize, CONV_SMEM);
    cudaFuncSetAttribute(attn_h, cudaFuncAttributeMaxDynamicSharedMemorySize, ATTN_SMEM);

    // Side stream + events: created once, host-side, outside any capture.
    static cudaStream_t s2 = nullptr;
    static cudaEvent_t evFork = nullptr, evW = nullptr, evDw = nullptr;
    if (!s2) {
        cudaStreamCreateWithFlags(&s2, cudaStreamNonBlocking);
        cudaEventCreateWithFlags(&evFork, cudaEventDisableTiming);
        cudaEventCreateWithFlags(&evW, cudaEventDisableTiming);
        cudaEventCreateWithFlags(&evDw, cudaEventDisableTiming);
    }

    dim3 tb(32, 8);
    dim3 tg(3, 16, 768);

    // ---- fork: weight prep + dwconv on s2 (cheap, overlaps img2seq/QKV) ----
    cudaEventRecord(evFork, 0);
    cudaStreamWaitEvent(s2, evFork, 0);
    wprep<<<1792, 256, 0, s2>>>(Wk, Wv, cWv, Wo, cWq, cWo, pww);
    cudaEventRecord(evW, s2);
    bnprep<<<2, 256, 0, s2>>>(bng, bnb, bnm, bnv);
    dwconv_bn<<<36864, 256, 0, s2>>>(x, dww, dwh);
    cudaEventRecord(evDw, s2);

    // ---- main chain (all compute serial here) ----
    img2seq<<<tg, tb>>>(x, h0);
    cudaStreamWaitEvent(0, evW, 0);   // weights ready
    gemm_h<<<dim3(12, 576), 256, GEMM_SMEM>>>(h0, wKVV, h0, nullptr, h1, h2, h3, 1, 0, 0);
    attn_h<<<dim3(8, 768), 192, ATTN_SMEM>>>(h0, h1, h2, h4);
    gemm_h<<<dim3(4, 576), 256, GEMM_SMEM>>>(h4, rWo, nullptr, nullptr, h1, h1, h1, 0, 0, 0);
    seq2img_hh<<<tg, tb>>>(h1, h2);
    gemm_h<<<dim3(4, 576), 256, GEMM_SMEM>>>(h2, rcWq, nullptr, cbq, h4, h4, h4, 2, 2, 2);
    attn_h<<<dim3(8, 768), 192, ATTN_SMEM>>>(h4, h3, h3, h1);
    gemm_h<<<dim3(4, 576), 256, GEMM_SMEM>>>(h1, rcWo, nullptr, nullptr, h2, h2, h2, 0, 0, 0);
    seq2img_hh<<<tg, tb>>>(h2, h4);   // cr -> half image layout
    cudaStreamWaitEvent(0, evDw, 0);  // dwconv output ready
    gemm_conv_h<<<dim3(72, 4, 8), 256, CONV_SMEM>>>(rpw, dwh, h4, out);
}